// round 5
// baseline (speedup 1.0000x reference)
#include <cuda_runtime.h>
#include <cuda_bf16.h>
#include <cstdint>

// Problem constants
constexpr int kB = 4;
constexpr int kT = 2048;
constexpr int kC = 1024;
constexpr int kM = kB * kT;          // 8192 rows of x
constexpr float kScale = 0.03125f;   // C^-0.5 = 1/32

// Smem geometry for the GEMM kernels (dynamic): two stages, hi/lo planes,
// 128 rows x 12 uint32 (8 used + 4 pad for bank-conflict-free fragments).
constexpr int kRowW   = 12;                       // words per row
constexpr int kPlaneW = 128 * kRowW;              // words per (stage,plane)
constexpr int kArrW   = 2 * 2 * kPlaneW;          // words per A or B array
constexpr size_t kSmemBytes = 2 * kArrW * sizeof(uint32_t);  // 98304 B

// Scratch (device globals: allocation-free rule)
__device__ float g_Q[kM * kC];
__device__ float g_K[kM * kC];
__device__ float g_V[kM * kC];
__device__ float g_S[(size_t)kB * kT * kT];

// ---------------------------------------------------------------------------
// bf16 helpers
// ---------------------------------------------------------------------------
__device__ __forceinline__ uint32_t bfpack(__nv_bfloat16 a, __nv_bfloat16 b) {
  return (uint32_t)__bfloat16_as_ushort(a) |
         ((uint32_t)__bfloat16_as_ushort(b) << 16);
}

// split x into hi (bf16 round) + lo (bf16 of residual); pack pairs
__device__ __forceinline__ void split2(float x0, float x1,
                                       uint32_t& hi, uint32_t& lo) {
  __nv_bfloat16 h0 = __float2bfloat16(x0);
  __nv_bfloat16 h1 = __float2bfloat16(x1);
  float r0 = x0 - __bfloat162float(h0);
  float r1 = x1 - __bfloat162float(h1);
  hi = bfpack(h0, h1);
  lo = bfpack(__float2bfloat16(r0), __float2bfloat16(r1));
}

__device__ __forceinline__ void mma16816(float* c, const uint32_t* a,
                                         const uint32_t* b) {
  asm volatile(
      "mma.sync.aligned.m16n8k16.row.col.f32.bf16.bf16.f32 "
      "{%0,%1,%2,%3}, {%4,%5,%6,%7}, {%8,%9}, {%0,%1,%2,%3};\n"
      : "+f"(c[0]), "+f"(c[1]), "+f"(c[2]), "+f"(c[3])
      : "r"(a[0]), "r"(a[1]), "r"(a[2]), "r"(a[3]), "r"(b[0]), "r"(b[1]));
}

// indexing into dynamic smem: arr[stage][plane][row][word]
__device__ __forceinline__ uint32_t& sm_at(uint32_t* base, int st, int pl,
                                           int row, int wd) {
  return base[(size_t)(st * 2 + pl) * kPlaneW + row * kRowW + wd];
}

// ---------------------------------------------------------------------------
// 128x128 CTA-tile GEMM, K-step 16, split-bf16 (3 mma passes), double-buffered.
// A is always [m][k] row-major (k contiguous), lda given.
// BNN = false: B is [n][k] (k contiguous)  -> C = A * B^T   (TN)
// BNN = true : B is [k][n] (n contiguous)  -> C = A * B     (NN)
// 8 warps in 2(M) x 4(N); each warp owns 64x32 = 4x4 m16n8 tiles.
// ---------------------------------------------------------------------------
template <bool BNN>
__device__ __forceinline__ void gemm128_bf16(const float* __restrict__ A,
                                             const float* __restrict__ B,
                                             int lda, int ldb, int kEnd,
                                             float (&acc)[4][4][4]) {
  extern __shared__ uint32_t smem_u32[];
  uint32_t* As = smem_u32;
  uint32_t* Bs = smem_u32 + kArrW;

  const int tid = threadIdx.x;
  const int lane = tid & 31;
  const int gid = lane >> 2;   // 0..7
  const int tig = lane & 3;    // 0..3
  const int w = tid >> 5;      // 0..7
  const int wr = w >> 2;       // 0..1  (M)
  const int wc = w & 3;        // 0..3  (N)

  float4 ra[2], rb[2];

  auto ldA = [&](int k0) {
#pragma unroll
    for (int p = 0; p < 2; ++p) {
      const int id = tid + p * 256;
      const int row = id >> 2, c4 = id & 3;
      ra[p] = *reinterpret_cast<const float4*>(A + (size_t)row * lda + k0 + c4 * 4);
    }
  };
  auto stA = [&](int st) {
#pragma unroll
    for (int p = 0; p < 2; ++p) {
      const int id = tid + p * 256;
      const int row = id >> 2, c4 = id & 3;
      uint32_t h01, l01, h23, l23;
      split2(ra[p].x, ra[p].y, h01, l01);
      split2(ra[p].z, ra[p].w, h23, l23);
      *reinterpret_cast<uint2*>(&sm_at(As, st, 0, row, c4 * 2)) = make_uint2(h01, h23);
      *reinterpret_cast<uint2*>(&sm_at(As, st, 1, row, c4 * 2)) = make_uint2(l01, l23);
    }
  };
  auto ldB = [&](int k0) {
    if (!BNN) {
#pragma unroll
      for (int p = 0; p < 2; ++p) {
        const int id = tid + p * 256;
        const int row = id >> 2, c4 = id & 3;
        rb[p] = *reinterpret_cast<const float4*>(B + (size_t)row * ldb + k0 + c4 * 4);
      }
    } else {
#pragma unroll
      for (int p = 0; p < 2; ++p) {
        const int id = tid + p * 256;
        const int kr = id & 15, nc = id >> 4;   // 16 k-rows x 32 n-quads
        rb[p] = *reinterpret_cast<const float4*>(B + (size_t)(k0 + kr) * ldb + nc * 4);
      }
    }
  };
  auto stB = [&](int st) {
    if (!BNN) {
#pragma unroll
      for (int p = 0; p < 2; ++p) {
        const int id = tid + p * 256;
        const int row = id >> 2, c4 = id & 3;
        uint32_t h01, l01, h23, l23;
        split2(rb[p].x, rb[p].y, h01, l01);
        split2(rb[p].z, rb[p].w, h23, l23);
        *reinterpret_cast<uint2*>(&sm_at(Bs, st, 0, row, c4 * 2)) = make_uint2(h01, h23);
        *reinterpret_cast<uint2*>(&sm_at(Bs, st, 1, row, c4 * 2)) = make_uint2(l01, l23);
      }
    } else {
      // transpose-store: [k][n] global -> Bs[n][k] (2B scalar stores)
      uint16_t* b16 = reinterpret_cast<uint16_t*>(Bs);
#pragma unroll
      for (int p = 0; p < 2; ++p) {
        const int id = tid + p * 256;
        const int kr = id & 15, nc = id >> 4;
        const float v[4] = {rb[p].x, rb[p].y, rb[p].z, rb[p].w};
#pragma unroll
        for (int j = 0; j < 4; ++j) {
          const int n = nc * 4 + j;
          __nv_bfloat16 h = __float2bfloat16(v[j]);
          __nv_bfloat16 l = __float2bfloat16(v[j] - __bfloat162float(h));
          b16[((size_t)(st * 2 + 0) * 128 + n) * (kRowW * 2) + kr] = __bfloat16_as_ushort(h);
          b16[((size_t)(st * 2 + 1) * 128 + n) * (kRowW * 2) + kr] = __bfloat16_as_ushort(l);
        }
      }
    }
  };

  ldA(0); ldB(0);
  stA(0); stB(0);
  __syncthreads();

  int buf = 0;
  for (int k0 = 0; k0 < kEnd; k0 += 16) {
    const bool hasNext = (k0 + 16) < kEnd;
    if (hasNext) { ldA(k0 + 16); ldB(k0 + 16); }

    // fragment loads (conflict-free by stride-12 construction)
    uint32_t afh[4][4], afl[4][4], bfh[4][2], bfl[4][2];
#pragma unroll
    for (int i = 0; i < 4; ++i) {
      const int r0 = wr * 64 + i * 16 + gid, r1 = r0 + 8;
      afh[i][0] = sm_at(As, buf, 0, r0, tig);     afh[i][1] = sm_at(As, buf, 0, r1, tig);
      afh[i][2] = sm_at(As, buf, 0, r0, tig + 4); afh[i][3] = sm_at(As, buf, 0, r1, tig + 4);
      afl[i][0] = sm_at(As, buf, 1, r0, tig);     afl[i][1] = sm_at(As, buf, 1, r1, tig);
      afl[i][2] = sm_at(As, buf, 1, r0, tig + 4); afl[i][3] = sm_at(As, buf, 1, r1, tig + 4);
    }
#pragma unroll
    for (int j = 0; j < 4; ++j) {
      const int n = wc * 32 + j * 8 + gid;
      bfh[j][0] = sm_at(Bs, buf, 0, n, tig); bfh[j][1] = sm_at(Bs, buf, 0, n, tig + 4);
      bfl[j][0] = sm_at(Bs, buf, 1, n, tig); bfl[j][1] = sm_at(Bs, buf, 1, n, tig + 4);
    }

#pragma unroll
    for (int i = 0; i < 4; ++i)
#pragma unroll
      for (int j = 0; j < 4; ++j) {
        mma16816(acc[i][j], afh[i], bfh[j]);  // hi*hi
        mma16816(acc[i][j], afh[i], bfl[j]);  // hi*lo
        mma16816(acc[i][j], afl[i], bfh[j]);  // lo*hi
      }

    if (hasNext) {
      stA(buf ^ 1); stB(buf ^ 1);
      __syncthreads();
      buf ^= 1;
    }
  }
}

// ---------------------------------------------------------------------------
// Kernel 1: Q/K/V projections. y = x @ W^T.  grid = (C/128, M/128, 3)
// ---------------------------------------------------------------------------
__global__ __launch_bounds__(256) void qkv_kernel(const float* __restrict__ x,
                                                  const float* __restrict__ Wk,
                                                  const float* __restrict__ Wq,
                                                  const float* __restrict__ Wv) {
  const int n0 = blockIdx.x * 128;
  const int m0 = blockIdx.y * 128;
  const float* W;
  float* out;
  if (blockIdx.z == 0)      { W = Wq; out = g_Q; }
  else if (blockIdx.z == 1) { W = Wk; out = g_K; }
  else                      { W = Wv; out = g_V; }

  float acc[4][4][4] = {};
  gemm128_bf16<false>(x + (size_t)m0 * kC, W + (size_t)n0 * kC, kC, kC, kC, acc);

  const int lane = threadIdx.x & 31, gid = lane >> 2, tig = lane & 3;
  const int w = threadIdx.x >> 5, wr = w >> 2, wc = w & 3;
#pragma unroll
  for (int i = 0; i < 4; ++i)
#pragma unroll
    for (int j = 0; j < 4; ++j) {
      const int r0 = m0 + wr * 64 + i * 16 + gid;
      const int c = n0 + wc * 32 + j * 8 + 2 * tig;
      *reinterpret_cast<float2*>(out + (size_t)r0 * kC + c) =
          make_float2(acc[i][j][0], acc[i][j][1]);
      *reinterpret_cast<float2*>(out + (size_t)(r0 + 8) * kC + c) =
          make_float2(acc[i][j][2], acc[i][j][3]);
    }
}

// ---------------------------------------------------------------------------
// Kernel 2: S = (Q K^T) * scale, causal mask.  grid = (T/128, T/128, B)
// ---------------------------------------------------------------------------
__global__ __launch_bounds__(256) void s_kernel() {
  if (blockIdx.x > blockIdx.y) return;  // fully-masked tile
  const int b = blockIdx.z;
  const int n0 = blockIdx.x * 128;  // key index s
  const int m0 = blockIdx.y * 128;  // query index t
  const float* Q = g_Q + (size_t)b * kT * kC;
  const float* K = g_K + (size_t)b * kT * kC;
  float* S = g_S + (size_t)b * kT * kT;

  float acc[4][4][4] = {};
  gemm128_bf16<false>(Q + (size_t)m0 * kC, K + (size_t)n0 * kC, kC, kC, kC, acc);

  const int lane = threadIdx.x & 31, gid = lane >> 2, tig = lane & 3;
  const int w = threadIdx.x >> 5, wr = w >> 2, wc = w & 3;
#pragma unroll
  for (int i = 0; i < 4; ++i)
#pragma unroll
    for (int j = 0; j < 4; ++j) {
      const int t0 = m0 + wr * 64 + i * 16 + gid;
      const int s0 = n0 + wc * 32 + j * 8 + 2 * tig;
#pragma unroll
      for (int half = 0; half < 2; ++half) {
        const int t = t0 + half * 8;
        const float v0 = acc[i][j][half * 2 + 0] * kScale;
        const float v1 = acc[i][j][half * 2 + 1] * kScale;
        *reinterpret_cast<float2*>(S + (size_t)t * kT + s0) =
            make_float2((s0 > t) ? -1e30f : v0, (s0 + 1 > t) ? -1e30f : v1);
      }
    }
}

// ---------------------------------------------------------------------------
// Kernel 3: row softmax; exact zeros above diagonal. grid = (B*T), block 256.
// ---------------------------------------------------------------------------
__global__ __launch_bounds__(256) void softmax_kernel() {
  const int row = blockIdx.x;
  const int b = row >> 11;
  const int t = row & (kT - 1);
  float* S = g_S + (size_t)b * kT * kT + (size_t)t * kT;
  const int tid = threadIdx.x;

  float v[8];
  float mx = -1e30f;
#pragma unroll
  for (int i = 0; i < 8; ++i) {
    const int idx = tid + i * 256;
    v[i] = (idx <= t) ? S[idx] : -1e30f;
    mx = fmaxf(mx, v[i]);
  }
  __shared__ float redm[8];
  for (int o = 16; o; o >>= 1) mx = fmaxf(mx, __shfl_xor_sync(0xffffffffu, mx, o));
  if ((tid & 31) == 0) redm[tid >> 5] = mx;
  __syncthreads();
  mx = redm[0];
#pragma unroll
  for (int i = 1; i < 8; ++i) mx = fmaxf(mx, redm[i]);

  float sum = 0.f;
  float p[8];
#pragma unroll
  for (int i = 0; i < 8; ++i) {
    const int idx = tid + i * 256;
    p[i] = (idx <= t) ? __expf(v[i] - mx) : 0.f;
    sum += p[i];
  }
  __shared__ float reds[8];
  for (int o = 16; o; o >>= 1) sum += __shfl_xor_sync(0xffffffffu, sum, o);
  if ((tid & 31) == 0) reds[tid >> 5] = sum;
  __syncthreads();
  sum = reds[0];
#pragma unroll
  for (int i = 1; i < 8; ++i) sum += reds[i];

  const float inv = 1.0f / sum;
#pragma unroll
  for (int i = 0; i < 8; ++i) S[tid + i * 256] = p[i] * inv;
}

// ---------------------------------------------------------------------------
// Kernel 4: O = P @ V (NN), causal K-truncation.  grid = (C/128, T/128, B)
// ---------------------------------------------------------------------------
__global__ __launch_bounds__(256) void pv_kernel(float* __restrict__ out) {
  const int b = blockIdx.z;
  const int n0 = blockIdx.x * 128;  // output channel d
  const int m0 = blockIdx.y * 128;  // query index t
  const float* P = g_S + (size_t)b * kT * kT;
  const float* V = g_V + (size_t)b * kT * kC;

  float acc[4][4][4] = {};
  // P[t,s] == 0 for s > t -> only k < m0 + 128 contributes.
  gemm128_bf16<true>(P + (size_t)m0 * kT, V + n0, kT, kC, m0 + 128, acc);

  const int lane = threadIdx.x & 31, gid = lane >> 2, tig = lane & 3;
  const int w = threadIdx.x >> 5, wr = w >> 2, wc = w & 3;
#pragma unroll
  for (int i = 0; i < 4; ++i)
#pragma unroll
    for (int j = 0; j < 4; ++j) {
      const int r0 = m0 + wr * 64 + i * 16 + gid;
      const int c = n0 + wc * 32 + j * 8 + 2 * tig;
      *reinterpret_cast<float2*>(out + ((size_t)b * kT + r0) * kC + c) =
          make_float2(acc[i][j][0], acc[i][j][1]);
      *reinterpret_cast<float2*>(out + ((size_t)b * kT + r0 + 8) * kC + c) =
          make_float2(acc[i][j][2], acc[i][j][3]);
    }
}

// ---------------------------------------------------------------------------
extern "C" void kernel_launch(void* const* d_in, const int* in_sizes, int n_in,
                              void* d_out, int out_size) {
  const float* x  = (const float*)d_in[0];
  const float* Wk = (const float*)d_in[1];
  const float* Wq = (const float*)d_in[2];
  const float* Wv = (const float*)d_in[3];
  float* out = (float*)d_out;

  // Opt in to >48KB dynamic smem (deterministic, idempotent, capture-safe:
  // not a stream operation and not an allocation).
  cudaFuncSetAttribute(qkv_kernel, cudaFuncAttributeMaxDynamicSharedMemorySize,
                       (int)kSmemBytes);
  cudaFuncSetAttribute(s_kernel, cudaFuncAttributeMaxDynamicSharedMemorySize,
                       (int)kSmemBytes);
  cudaFuncSetAttribute(pv_kernel, cudaFuncAttributeMaxDynamicSharedMemorySize,
                       (int)kSmemBytes);

  dim3 blk(256);
  qkv_kernel<<<dim3(kC / 128, kM / 128, 3), blk, kSmemBytes>>>(x, Wk, Wq, Wv);
  s_kernel<<<dim3(kT / 128, kT / 128, kB), blk, kSmemBytes>>>();
  softmax_kernel<<<dim3(kM), blk>>>();
  pv_kernel<<<dim3(kC / 128, kT / 128, kB), blk, kSmemBytes>>>(out);
}

// round 6
// speedup vs baseline: 1.8889x; 1.8889x over previous
#include <cuda_runtime.h>
#include <cuda_bf16.h>
#include <cstdint>

constexpr int kB = 4, kT = 2048, kC = 1024, kM = kB * kT;
constexpr float kScale = 0.03125f;   // C^-0.5

// ---- packed bf16 hi/lo planes (uint32 = 2 bf16, k-contiguous rows) ----
__device__ __align__(16) uint32_t g_x2[2][kM][kC / 2];
__device__ __align__(16) uint32_t g_W2[3][2][kC][kC / 2];   // [0]=Wq [1]=Wk [2]=Wv
__device__ __align__(16) uint32_t g_Q2[2][kM][kC / 2];
__device__ __align__(16) uint32_t g_K2[2][kM][kC / 2];
__device__ __align__(16) uint32_t g_V2[2][kB][kC][kT / 2];  // transposed: [d][s]
__device__ __align__(16) uint32_t g_P2[2][kB][kT][kT / 2];
__device__ float g_S[(size_t)kB * kT * kT];

// Smem: 3 stages x (A hi, A lo, B hi, B lo), each plane 128 rows x 12 words
constexpr int kRowW = 12;
constexpr int kPlaneW = 128 * kRowW;          // 1536 words
constexpr int kStageW = 4 * kPlaneW;          // 6144 words = 24KB
constexpr int kSmemBytes = 3 * kStageW * 4;   // 73728 B

// ---------------------------------------------------------------------------
__device__ __forceinline__ uint32_t bfpack(__nv_bfloat16 a, __nv_bfloat16 b) {
  return (uint32_t)__bfloat16_as_ushort(a) |
         ((uint32_t)__bfloat16_as_ushort(b) << 16);
}
__device__ __forceinline__ void packHL(float a, float b, uint32_t& h, uint32_t& l) {
  __nv_bfloat16 ha = __float2bfloat16(a), hb = __float2bfloat16(b);
  h = bfpack(ha, hb);
  l = bfpack(__float2bfloat16(a - __bfloat162float(ha)),
             __float2bfloat16(b - __bfloat162float(hb)));
}
__device__ __forceinline__ void splitHL16(float a, uint16_t& h, uint16_t& l) {
  __nv_bfloat16 hb = __float2bfloat16(a);
  h = __bfloat16_as_ushort(hb);
  l = __bfloat16_as_ushort(__float2bfloat16(a - __bfloat162float(hb)));
}
__device__ __forceinline__ void mma16816(float* c, const uint32_t* a,
                                         const uint32_t* b) {
  asm volatile(
      "mma.sync.aligned.m16n8k16.row.col.f32.bf16.bf16.f32 "
      "{%0,%1,%2,%3}, {%4,%5,%6,%7}, {%8,%9}, {%0,%1,%2,%3};\n"
      : "+f"(c[0]), "+f"(c[1]), "+f"(c[2]), "+f"(c[3])
      : "r"(a[0]), "r"(a[1]), "r"(a[2]), "r"(a[3]), "r"(b[0]), "r"(b[1]));
}
__device__ __forceinline__ void ldsm4(uint32_t addr, uint32_t& r0, uint32_t& r1,
                                      uint32_t& r2, uint32_t& r3) {
  asm volatile(
      "ldmatrix.sync.aligned.m8n8.x4.shared.b16 {%0,%1,%2,%3}, [%4];\n"
      : "=r"(r0), "=r"(r1), "=r"(r2), "=r"(r3) : "r"(addr));
}
__device__ __forceinline__ void cpasync16(uint32_t dst, const void* src) {
  asm volatile("cp.async.cg.shared.global [%0], [%1], 16;\n" ::"r"(dst),
               "l"(src) : "memory");
}
__device__ __forceinline__ void cpcommit() {
  asm volatile("cp.async.commit_group;\n" ::: "memory");
}
__device__ __forceinline__ void cpwait1() {
  asm volatile("cp.async.wait_group 1;\n" ::: "memory");
}
__device__ __forceinline__ void cpwait0() {
  asm volatile("cp.async.wait_group 0;\n" ::: "memory");
}

// ---------------------------------------------------------------------------
// TN GEMM core: C[128,128] += A[128,K] * B[128,K]^T, A/B packed bf16 hi/lo.
// 8 warps 2(M)x4(N), each warp 64x32 = 4x4 m16n8 tiles, 3 mma passes (split).
// 3-stage cp.async pipeline, ldmatrix fragment loads.
// ---------------------------------------------------------------------------
__device__ __forceinline__ void gemm_tn(const uint32_t* __restrict__ Ahi,
                                        const uint32_t* __restrict__ Alo,
                                        const uint32_t* __restrict__ Bhi,
                                        const uint32_t* __restrict__ Blo,
                                        int ldwA, int ldwB, int nIter,
                                        float (&acc)[4][4][4]) {
  extern __shared__ uint32_t sm[];
  const uint32_t smBase = (uint32_t)__cvta_generic_to_shared(sm);
  const int tid = threadIdx.x, lane = tid & 31;
  const int w = tid >> 5, wr = w >> 2, wc = w & 3;
  const int cprow = tid >> 1, cpch = (tid & 1) * 4;  // 128 rows x 2 16B chunks
  const int rIT = (lane & 7) + ((lane >> 3) & 1) * 8;  // ldmatrix row-in-tile
  const int wd = (lane >> 4) * 4;                      // ldmatrix word offset

  auto issue = [&](int it) {
    const uint32_t base = smBase + (it % 3) * (kStageW * 4);
    const uint32_t d = base + (cprow * kRowW + cpch) * 4;
    const size_t oa = (size_t)cprow * ldwA + it * 8 + cpch;
    const size_t ob = (size_t)cprow * ldwB + it * 8 + cpch;
    cpasync16(d, Ahi + oa);
    cpasync16(d + kPlaneW * 4, Alo + oa);
    cpasync16(d + 2 * kPlaneW * 4, Bhi + ob);
    cpasync16(d + 3 * kPlaneW * 4, Blo + ob);
    cpcommit();
  };

  issue(0);
  if (nIter > 1) issue(1);

  for (int it = 0; it < nIter; ++it) {
    if (it + 2 <= nIter) cpwait1(); else cpwait0();
    __syncthreads();
    if (it + 2 < nIter) issue(it + 2);

    const uint32_t base = smBase + (it % 3) * (kStageW * 4);

    // B fragments: 2 x (ldmatrix.x4 covers j-pair) per plane
    uint32_t bfh[4][2], bfl[4][2];
#pragma unroll
    for (int jp = 0; jp < 2; ++jp) {
      const int row = wc * 32 + jp * 16 + rIT;
      const uint32_t a = base + (2 * kPlaneW + row * kRowW + wd) * 4;
      uint32_t r0, r1, r2, r3;
      ldsm4(a, r0, r1, r2, r3);
      bfh[jp * 2][0] = r0; bfh[jp * 2 + 1][0] = r1;
      bfh[jp * 2][1] = r2; bfh[jp * 2 + 1][1] = r3;
      ldsm4(a + kPlaneW * 4, r0, r1, r2, r3);
      bfl[jp * 2][0] = r0; bfl[jp * 2 + 1][0] = r1;
      bfl[jp * 2][1] = r2; bfl[jp * 2 + 1][1] = r3;
    }

#pragma unroll
    for (int i = 0; i < 4; ++i) {
      const int row = wr * 64 + i * 16 + rIT;
      const uint32_t a = base + (row * kRowW + wd) * 4;
      uint32_t ah[4], al[4];
      ldsm4(a, ah[0], ah[1], ah[2], ah[3]);
      ldsm4(a + kPlaneW * 4, al[0], al[1], al[2], al[3]);
#pragma unroll
      for (int j = 0; j < 4; ++j) {
        mma16816(acc[i][j], ah, bfh[j]);  // hi*hi
        mma16816(acc[i][j], ah, bfl[j]);  // hi*lo
        mma16816(acc[i][j], al, bfh[j]);  // lo*hi
      }
    }
  }
}

// ---------------------------------------------------------------------------
// Convert fp32 -> packed bf16 hi/lo planes. which: 0=x, 1=Wq, 2=Wk, 3=Wv
// ---------------------------------------------------------------------------
__global__ __launch_bounds__(256) void convert_kernel(
    const float* __restrict__ src, int which, int nPairs) {
  uint32_t *hi, *lo;
  if (which == 0)      { hi = &g_x2[0][0][0];    lo = &g_x2[1][0][0]; }
  else if (which == 1) { hi = &g_W2[0][0][0][0]; lo = &g_W2[0][1][0][0]; }
  else if (which == 2) { hi = &g_W2[1][0][0][0]; lo = &g_W2[1][1][0][0]; }
  else                 { hi = &g_W2[2][0][0][0]; lo = &g_W2[2][1][0][0]; }
  const int i = blockIdx.x * 256 + threadIdx.x;
  if (i >= nPairs) return;
  const float2 v = reinterpret_cast<const float2*>(src)[i];
  uint32_t h, l;
  packHL(v.x, v.y, h, l);
  hi[i] = h; lo[i] = l;
}

// ---------------------------------------------------------------------------
// Kernel 1: Q/K/V projections. grid = (8, 64, 3). z: 0->Q, 1->K, 2->V(transp.)
// ---------------------------------------------------------------------------
__global__ __launch_bounds__(256, 2) void qkv_kernel() {
  const int n0 = blockIdx.x * 128, m0 = blockIdx.y * 128, z = blockIdx.z;

  float acc[4][4][4] = {};
  gemm_tn(&g_x2[0][m0][0], &g_x2[1][m0][0],
          &g_W2[z][0][n0][0], &g_W2[z][1][n0][0],
          kC / 2, kC / 2, kC / 16, acc);

  const int lane = threadIdx.x & 31, gid = lane >> 2, tig = lane & 3;
  const int w = threadIdx.x >> 5, wr = w >> 2, wc = w & 3;

  if (z < 2) {
    uint32_t (*oh)[kC / 2] = (z == 0) ? g_Q2[0] : g_K2[0];
    uint32_t (*ol)[kC / 2] = (z == 0) ? g_Q2[1] : g_K2[1];
#pragma unroll
    for (int i = 0; i < 4; ++i)
#pragma unroll
      for (int j = 0; j < 4; ++j) {
        const int r0 = m0 + wr * 64 + i * 16 + gid;
        const int cw = (n0 + wc * 32 + j * 8 + 2 * tig) >> 1;
        uint32_t h, l;
        packHL(acc[i][j][0], acc[i][j][1], h, l);
        oh[r0][cw] = h; ol[r0][cw] = l;
        packHL(acc[i][j][2], acc[i][j][3], h, l);
        oh[r0 + 8][cw] = h; ol[r0 + 8][cw] = l;
      }
  } else {
    // V: transpose 128(s) x 128(d) tile through smem -> g_V2[plane][b][d][s/2]
    extern __shared__ uint32_t sm[];
    uint16_t* s16 = reinterpret_cast<uint16_t*>(sm);
    constexpr int LP = 130;  // padded row (uint16) per d
    __syncthreads();  // pipeline fully drained; safe to reuse smem
#pragma unroll
    for (int i = 0; i < 4; ++i)
#pragma unroll
      for (int j = 0; j < 4; ++j) {
        const int r = wr * 64 + i * 16 + gid;     // s local
        const int c = wc * 32 + j * 8 + 2 * tig;  // d local
        uint16_t h, l;
        splitHL16(acc[i][j][0], h, l);
        s16[c * LP + r] = h; s16[128 * LP + c * LP + r] = l;
        splitHL16(acc[i][j][1], h, l);
        s16[(c + 1) * LP + r] = h; s16[128 * LP + (c + 1) * LP + r] = l;
        splitHL16(acc[i][j][2], h, l);
        s16[c * LP + r + 8] = h; s16[128 * LP + c * LP + r + 8] = l;
        splitHL16(acc[i][j][3], h, l);
        s16[(c + 1) * LP + r + 8] = h; s16[128 * LP + (c + 1) * LP + r + 8] = l;
      }
    __syncthreads();
    const int b = m0 >> 11;
    const int sw0 = (m0 & (kT - 1)) >> 1;
    for (int t = threadIdx.x; t < 128 * 64; t += 256) {
      const int d = t >> 6, wi = t & 63;
      const uint32_t h = (uint32_t)s16[d * LP + 2 * wi] |
                         ((uint32_t)s16[d * LP + 2 * wi + 1] << 16);
      const uint32_t l = (uint32_t)s16[128 * LP + d * LP + 2 * wi] |
                         ((uint32_t)s16[128 * LP + d * LP + 2 * wi + 1] << 16);
      g_V2[0][b][n0 + d][sw0 + wi] = h;
      g_V2[1][b][n0 + d][sw0 + wi] = l;
    }
  }
}

// ---------------------------------------------------------------------------
// Kernel 2: S = (Q K^T)*scale with causal mask. grid = (16, 16, 4)
// ---------------------------------------------------------------------------
__global__ __launch_bounds__(256, 2) void s_kernel() {
  if (blockIdx.x > blockIdx.y) return;
  const int b = blockIdx.z;
  const int n0 = blockIdx.x * 128, m0 = blockIdx.y * 128;
  float* S = g_S + (size_t)b * kT * kT;

  float acc[4][4][4] = {};
  gemm_tn(&g_Q2[0][b * kT + m0][0], &g_Q2[1][b * kT + m0][0],
          &g_K2[0][b * kT + n0][0], &g_K2[1][b * kT + n0][0],
          kC / 2, kC / 2, kC / 16, acc);

  const int lane = threadIdx.x & 31, gid = lane >> 2, tig = lane & 3;
  const int w = threadIdx.x >> 5, wr = w >> 2, wc = w & 3;
#pragma unroll
  for (int i = 0; i < 4; ++i)
#pragma unroll
    for (int j = 0; j < 4; ++j) {
      const int t0 = m0 + wr * 64 + i * 16 + gid;
      const int s0 = n0 + wc * 32 + j * 8 + 2 * tig;
#pragma unroll
      for (int half = 0; half < 2; ++half) {
        const int t = t0 + half * 8;
        const float v0 = acc[i][j][half * 2 + 0] * kScale;
        const float v1 = acc[i][j][half * 2 + 1] * kScale;
        *reinterpret_cast<float2*>(S + (size_t)t * kT + s0) =
            make_float2((s0 > t) ? -1e30f : v0, (s0 + 1 > t) ? -1e30f : v1);
      }
    }
}

// ---------------------------------------------------------------------------
// Kernel 3: row softmax; writes P as packed bf16 hi/lo (zeros above diagonal).
// ---------------------------------------------------------------------------
__global__ __launch_bounds__(256) void softmax_kernel() {
  const int row = blockIdx.x, b = row >> 11, t = row & (kT - 1);
  const float* S = g_S + (size_t)b * kT * kT + (size_t)t * kT;
  const int tid = threadIdx.x;
  const int base = tid * 8;

  const float4 u0 = *reinterpret_cast<const float4*>(S + base);
  const float4 u1 = *reinterpret_cast<const float4*>(S + base + 4);
  float v[8] = {u0.x, u0.y, u0.z, u0.w, u1.x, u1.y, u1.z, u1.w};
  float mx = -1e30f;
#pragma unroll
  for (int i = 0; i < 8; ++i) {
    v[i] = (base + i <= t) ? v[i] : -1e30f;
    mx = fmaxf(mx, v[i]);
  }
  __shared__ float redm[8];
  for (int o = 16; o; o >>= 1) mx = fmaxf(mx, __shfl_xor_sync(0xffffffffu, mx, o));
  if ((tid & 31) == 0) redm[tid >> 5] = mx;
  __syncthreads();
  mx = redm[0];
#pragma unroll
  for (int i = 1; i < 8; ++i) mx = fmaxf(mx, redm[i]);

  float sum = 0.f, p[8];
#pragma unroll
  for (int i = 0; i < 8; ++i) {
    p[i] = (base + i <= t) ? __expf(v[i] - mx) : 0.f;
    sum += p[i];
  }
  __shared__ float reds[8];
  for (int o = 16; o; o >>= 1) sum += __shfl_xor_sync(0xffffffffu, sum, o);
  if ((tid & 31) == 0) reds[tid >> 5] = sum;
  __syncthreads();
  sum = reds[0];
#pragma unroll
  for (int i = 1; i < 8; ++i) sum += reds[i];
  const float inv = 1.0f / sum;

  uint32_t h[4], l[4];
#pragma unroll
  for (int k = 0; k < 4; ++k)
    packHL(p[2 * k] * inv, p[2 * k + 1] * inv, h[k], l[k]);
  *reinterpret_cast<uint4*>(&g_P2[0][b][t][tid * 4]) = make_uint4(h[0], h[1], h[2], h[3]);
  *reinterpret_cast<uint4*>(&g_P2[1][b][t][tid * 4]) = make_uint4(l[0], l[1], l[2], l[3]);
}

// ---------------------------------------------------------------------------
// Kernel 4: O = P @ Vt^T (TN), causal K-truncation. grid = (8, 16, 4)
// m-tiles reversed so heaviest run first.
// ---------------------------------------------------------------------------
__global__ __launch_bounds__(256, 2) void pv_kernel(float* __restrict__ out) {
  const int b = blockIdx.z;
  const int n0 = blockIdx.x * 128;
  const int m0 = (gridDim.y - 1 - blockIdx.y) * 128;

  float acc[4][4][4] = {};
  gemm_tn(&g_P2[0][b][m0][0], &g_P2[1][b][m0][0],
          &g_V2[0][b][n0][0], &g_V2[1][b][n0][0],
          kT / 2, kT / 2, (m0 + 128) / 16, acc);

  const int lane = threadIdx.x & 31, gid = lane >> 2, tig = lane & 3;
  const int w = threadIdx.x >> 5, wr = w >> 2, wc = w & 3;
#pragma unroll
  for (int i = 0; i < 4; ++i)
#pragma unroll
    for (int j = 0; j < 4; ++j) {
      const int r0 = m0 + wr * 64 + i * 16 + gid;
      const int c = n0 + wc * 32 + j * 8 + 2 * tig;
      *reinterpret_cast<float2*>(out + ((size_t)b * kT + r0) * kC + c) =
          make_float2(acc[i][j][0], acc[i][j][1]);
      *reinterpret_cast<float2*>(out + ((size_t)b * kT + r0 + 8) * kC + c) =
          make_float2(acc[i][j][2], acc[i][j][3]);
    }
}

// ---------------------------------------------------------------------------
extern "C" void kernel_launch(void* const* d_in, const int* in_sizes, int n_in,
                              void* d_out, int out_size) {
  const float* x  = (const float*)d_in[0];
  const float* Wk = (const float*)d_in[1];
  const float* Wq = (const float*)d_in[2];
  const float* Wv = (const float*)d_in[3];
  float* out = (float*)d_out;

  cudaFuncSetAttribute(qkv_kernel, cudaFuncAttributeMaxDynamicSharedMemorySize, kSmemBytes);
  cudaFuncSetAttribute(s_kernel, cudaFuncAttributeMaxDynamicSharedMemorySize, kSmemBytes);
  cudaFuncSetAttribute(pv_kernel, cudaFuncAttributeMaxDynamicSharedMemorySize, kSmemBytes);

  convert_kernel<<<kM * kC / 2 / 256, 256>>>(x, 0, kM * kC / 2);
  convert_kernel<<<kC * kC / 2 / 256, 256>>>(Wq, 1, kC * kC / 2);
  convert_kernel<<<kC * kC / 2 / 256, 256>>>(Wk, 2, kC * kC / 2);
  convert_kernel<<<kC * kC / 2 / 256, 256>>>(Wv, 3, kC * kC / 2);

  dim3 blk(256);
  qkv_kernel<<<dim3(8, 64, 3), blk, kSmemBytes>>>();
  s_kernel<<<dim3(16, 16, 4), blk, kSmemBytes>>>();
  softmax_kernel<<<kM, blk>>>();
  pv_kernel<<<dim3(8, 16, 4), blk, kSmemBytes>>>(out);
}